// round 2
// baseline (speedup 1.0000x reference)
#include <cuda_runtime.h>
#include <cstdint>
#include <cstddef>

#define NROWS 8192
#define CDIM  128

// ---------------- device scratch (no allocations allowed) ----------------
__device__ float g_dinv[NROWS];                  // D^-1/2
__device__ float g_zT[CDIM * NROWS];             // zT[c][j] = dinv_j * (x W^T)_{j,c}, tf32-rounded
__device__ float g_z[NROWS * CDIM];              // z[j][c]  (row-major, full fp32)
__device__ float g_part[4 * NROWS * CDIM];       // split-K partials

// ---------------- helpers ----------------
__device__ __forceinline__ uint32_t smem_u32(const void* p) {
    uint32_t a;
    asm("{ .reg .u64 t; cvta.to.shared.u64 t, %1; cvt.u32.u64 %0, t; }" : "=r"(a) : "l"(p));
    return a;
}

#define CP_ASYNC16(dst, src) \
    asm volatile("cp.async.cg.shared.global [%0], [%1], 16;" :: "r"(dst), "l"(src) : "memory")
#define CP_COMMIT() asm volatile("cp.async.commit_group;" ::: "memory")
#define CP_WAIT2()  asm volatile("cp.async.wait_group 2;" ::: "memory")

__device__ __forceinline__ uint32_t f2tf32(float x) {
    uint32_t u;
    asm("cvt.rna.tf32.f32 %0, %1;" : "=r"(u) : "f"(x));
    return u;
}

__device__ __forceinline__ void mma_tf32(float& d0, float& d1, float& d2, float& d3,
                                         uint32_t a0, uint32_t a1, uint32_t a2, uint32_t a3,
                                         uint32_t b0, uint32_t b1) {
    asm volatile(
        "mma.sync.aligned.m16n8k8.row.col.f32.tf32.tf32.f32 "
        "{%0,%1,%2,%3}, {%4,%5,%6,%7}, {%8,%9}, {%0,%1,%2,%3};"
        : "+f"(d0), "+f"(d1), "+f"(d2), "+f"(d3)
        : "r"(a0), "r"(a1), "r"(a2), "r"(a3), "r"(b0), "r"(b1));
}

// ============================================================================
// K1: dinv[i] = rsqrt(1 + sum_j adj[i][j])
// ============================================================================
__global__ void __launch_bounds__(256) k1_rowsum(const float* __restrict__ adj) {
    const int row = blockIdx.x;
    const float4* p = reinterpret_cast<const float4*>(adj + (size_t)row * NROWS);
    float s = 0.0f;
    #pragma unroll 4
    for (int i = threadIdx.x; i < NROWS / 4; i += 256) {
        float4 v = p[i];
        s += (v.x + v.y) + (v.z + v.w);
    }
    #pragma unroll
    for (int o = 16; o > 0; o >>= 1) s += __shfl_xor_sync(0xFFFFFFFFu, s, o);
    __shared__ float ws[8];
    if ((threadIdx.x & 31) == 0) ws[threadIdx.x >> 5] = s;
    __syncthreads();
    if (threadIdx.x == 0) {
        float t = 0.0f;
        #pragma unroll
        for (int i = 0; i < 8; i++) t += ws[i];
        g_dinv[row] = rsqrtf(t + 1.0f);
    }
}

// ============================================================================
// K2: zT[c][j] = tf32(dinv_j * sum_k x[j][k]*W[c][k]);  z[j][c] = same (fp32)
// 128 threads (thread = channel c), 16 rows per block
// ============================================================================
__global__ void __launch_bounds__(128) k2_xw(const float* __restrict__ x,
                                             const float* __restrict__ W) {
    extern __shared__ float sh2[];
    float* Ws = sh2;                 // [128][132]
    float* xs = sh2 + 128 * 132;     // [16][128]
    const int c = threadIdx.x;
    const int j0 = blockIdx.x * 16;

    for (int idx = c; idx < 128 * 128; idx += 128)
        Ws[(idx >> 7) * 132 + (idx & 127)] = W[idx];
    for (int idx = c; idx < 16 * 128; idx += 128)
        xs[idx] = x[(size_t)(j0 + (idx >> 7)) * 128 + (idx & 127)];
    __syncthreads();

    float acc[16];
    #pragma unroll
    for (int r = 0; r < 16; r++) acc[r] = 0.0f;
    for (int k = 0; k < 128; k += 4) {
        float4 wv = *reinterpret_cast<const float4*>(&Ws[c * 132 + k]);
        #pragma unroll
        for (int r = 0; r < 16; r++) {
            float4 xv = *reinterpret_cast<const float4*>(&xs[r * 128 + k]);
            acc[r] += xv.x * wv.x + xv.y * wv.y + xv.z * wv.z + xv.w * wv.w;
        }
    }
    float v[16];
    #pragma unroll
    for (int r = 0; r < 16; r++) {
        v[r] = g_dinv[j0 + r] * acc[r];
        g_z[(size_t)(j0 + r) * 128 + c] = v[r];     // row-major, coalesced per r
    }
    #pragma unroll
    for (int m = 0; m < 4; m++) {
        float4 q;
        q.x = __uint_as_float(f2tf32(v[4 * m + 0]));
        q.y = __uint_as_float(f2tf32(v[4 * m + 1]));
        q.z = __uint_as_float(f2tf32(v[4 * m + 2]));
        q.w = __uint_as_float(f2tf32(v[4 * m + 3]));
        *reinterpret_cast<float4*>(&g_zT[(size_t)c * NROWS + j0 + 4 * m]) = q;
    }
}

// ============================================================================
// K3: split-K tf32 mma.sync GEMM: part[ks] += adj[tile, kslice] @ z[kslice, :]
// 256 CTAs (64 tiles x 4 ksplits), 256 threads, BM=BN=128, BK=32, 3 stages
// ============================================================================
static constexpr int BK = 32;
static constexpr int NSTAGE = 3;
static constexpr int STAGE_FLOATS = 2 * 128 * BK;        // A + B = 8192 floats
static constexpr int SMEM_K3 = NSTAGE * STAGE_FLOATS * 4;  // 98304 B

__device__ __forceinline__ void k3_issue(int kt, int m0, int kbase, int tid,
                                         uint32_t smem_base,
                                         const float* __restrict__ adj) {
    const int st = kt % NSTAGE;
    const uint32_t sA = smem_base + st * (STAGE_FLOATS * 4);
    const uint32_t sB = sA + 128 * BK * 4;
    const int k0 = kbase + kt * BK;
    #pragma unroll
    for (int it = 0; it < 4; it++) {
        const int ch = tid + it * 256;          // 0..1023
        const int r = ch >> 3, q = ch & 7;
        const float* src = adj + (size_t)(m0 + r) * NROWS + k0 + q * 4;
        CP_ASYNC16(sA + r * 128 + ((q ^ (r & 7)) << 4), src);
    }
    #pragma unroll
    for (int it = 0; it < 4; it++) {
        const int ch = tid + it * 256;
        const int r = ch >> 3, q = ch & 7;
        const float* src = g_zT + (size_t)r * NROWS + k0 + q * 4;
        CP_ASYNC16(sB + r * 128 + ((q ^ (r & 7)) << 4), src);
    }
}

__global__ void __launch_bounds__(256, 2) k3_gemm(const float* __restrict__ adj) {
    extern __shared__ float smf[];
    const uint32_t smem_base = smem_u32(smf);
    const int tid = threadIdx.x;
    const int wid = tid >> 5, lane = tid & 31;
    const int gid = lane >> 2, tig = lane & 3;
    const int wm = wid & 3;          // M warp tile (32 rows)
    const int wn = wid >> 2;         // N warp tile (64 cols)

    const int tile = blockIdx.x & 63;
    const int ks = blockIdx.x >> 6;
    const int m0 = tile * 128;
    const int kbase = ks * 2048;
    const int NK = 2048 / BK;        // 64

    float acc[2][8][4];
    #pragma unroll
    for (int i = 0; i < 2; i++)
        #pragma unroll
        for (int j = 0; j < 8; j++)
            #pragma unroll
            for (int t = 0; t < 4; t++) acc[i][j][t] = 0.0f;

    // prologue: stages 0,1
    k3_issue(0, m0, kbase, tid, smem_base, adj); CP_COMMIT();
    k3_issue(1, m0, kbase, tid, smem_base, adj); CP_COMMIT();

    for (int kt = 0; kt < NK; kt++) {
        if (kt + 2 < NK) k3_issue(kt + 2, m0, kbase, tid, smem_base, adj);
        CP_COMMIT();
        CP_WAIT2();
        __syncthreads();

        const float* As = smf + (kt % NSTAGE) * STAGE_FLOATS;
        const float* Bs = As + 128 * BK;

        #pragma unroll
        for (int k8 = 0; k8 < 4; k8++) {
            const int kb = k8 * 8;
            uint32_t a[2][4], b[8][2];
            #pragma unroll
            for (int mt = 0; mt < 2; mt++) {
                const int r0 = wm * 32 + mt * 16 + gid;
                const int r1 = r0 + 8;
                const int kk = kb + tig;
                const int sw0 = (r0 & 7) << 2, sw1 = (r1 & 7) << 2;
                a[mt][0] = f2tf32(As[r0 * 32 + (kk ^ sw0)]);
                a[mt][1] = f2tf32(As[r1 * 32 + (kk ^ sw1)]);
                a[mt][2] = f2tf32(As[r0 * 32 + ((kk + 4) ^ sw0)]);
                a[mt][3] = f2tf32(As[r1 * 32 + ((kk + 4) ^ sw1)]);
            }
            #pragma unroll
            for (int nt = 0; nt < 8; nt++) {
                const int n = wn * 64 + nt * 8 + gid;
                const int kk = kb + tig;
                const int sw = (n & 7) << 2;
                b[nt][0] = __float_as_uint(Bs[n * 32 + (kk ^ sw)]);
                b[nt][1] = __float_as_uint(Bs[n * 32 + ((kk + 4) ^ sw)]);
            }
            #pragma unroll
            for (int mt = 0; mt < 2; mt++)
                #pragma unroll
                for (int nt = 0; nt < 8; nt++)
                    mma_tf32(acc[mt][nt][0], acc[mt][nt][1], acc[mt][nt][2], acc[mt][nt][3],
                             a[mt][0], a[mt][1], a[mt][2], a[mt][3],
                             b[nt][0], b[nt][1]);
        }
        __syncthreads();
    }

    // write partials (float2, 8B aligned)
    float* part = g_part + (size_t)ks * (NROWS * CDIM) + (size_t)m0 * CDIM;
    #pragma unroll
    for (int mt = 0; mt < 2; mt++) {
        const int r0 = wm * 32 + mt * 16 + gid;
        #pragma unroll
        for (int nt = 0; nt < 8; nt++) {
            const int col = wn * 64 + nt * 8 + tig * 2;
            *reinterpret_cast<float2*>(part + (size_t)r0 * 128 + col) =
                make_float2(acc[mt][nt][0], acc[mt][nt][1]);
            *reinterpret_cast<float2*>(part + (size_t)(r0 + 8) * 128 + col) =
                make_float2(acc[mt][nt][2], acc[mt][nt][3]);
        }
    }
}

// ============================================================================
// K4: out[i][c] = dinv_i * (sum_s part[s][i][c] + z[i][c]) + b[c]
// ============================================================================
__global__ void __launch_bounds__(256) k4_reduce(const float* __restrict__ bias,
                                                 float* __restrict__ out) {
    const int idx = blockIdx.x * 256 + threadIdx.x;   // 0..262143
    const int i = idx >> 5;
    const int c4 = (idx & 31) * 4;
    const size_t off = (size_t)i * 128 + c4;

    float4 s = *reinterpret_cast<const float4*>(g_z + off);
    #pragma unroll
    for (int sp = 0; sp < 4; sp++) {
        float4 p = *reinterpret_cast<const float4*>(g_part + (size_t)sp * (NROWS * CDIM) + off);
        s.x += p.x; s.y += p.y; s.z += p.z; s.w += p.w;
    }
    const float di = g_dinv[i];
    const float4 bb = *reinterpret_cast<const float4*>(bias + c4);
    float4 o;
    o.x = di * s.x + bb.x;
    o.y = di * s.y + bb.y;
    o.z = di * s.z + bb.z;
    o.w = di * s.w + bb.w;
    *reinterpret_cast<float4*>(out + off) = o;
}

// ============================================================================
// launch
// ============================================================================
extern "C" void kernel_launch(void* const* d_in, const int* in_sizes, int n_in,
                              void* d_out, int out_size) {
    (void)in_sizes; (void)n_in; (void)out_size;
    const float* x   = (const float*)d_in[0];   // (8192, 128)
    const float* adj = (const float*)d_in[1];   // (8192, 8192)
    const float* W   = (const float*)d_in[2];   // (128, 128)
    const float* b   = (const float*)d_in[3];   // (128,)
    float* out = (float*)d_out;

    const int smem_k2 = (128 * 132 + 16 * 128) * 4;
    cudaFuncSetAttribute(k2_xw, cudaFuncAttributeMaxDynamicSharedMemorySize, smem_k2);
    cudaFuncSetAttribute(k3_gemm, cudaFuncAttributeMaxDynamicSharedMemorySize, SMEM_K3);

    k1_rowsum<<<NROWS, 256>>>(adj);
    k2_xw<<<NROWS / 16, 128, smem_k2>>>(x, W);
    k3_gemm<<<256, 256, SMEM_K3>>>(adj);
    k4_reduce<<<NROWS * CDIM / 4 / 256, 256>>>(b, out);
}

// round 4
// speedup vs baseline: 1.1770x; 1.1770x over previous
#include <cuda_runtime.h>
#include <cuda_fp16.h>
#include <cstdint>
#include <cstddef>

#define NROWS 8192
#define CDIM  128

// ---------------- device scratch (no allocations allowed) ----------------
__device__ float  g_dinv[NROWS];                 // D^-1/2
__device__ __half g_zT_h[CDIM * NROWS];          // zT[c][j] = dinv_j*(xW^T)_{j,c}, fp16
__device__ float  g_z[NROWS * CDIM];             // z[j][c] fp32 (self-loop term)
__device__ float  g_part[4 * NROWS * CDIM];      // split-K partials

// ---------------- helpers ----------------
__device__ __forceinline__ uint32_t smem_u32(const void* p) {
    uint32_t a;
    asm("{ .reg .u64 t; cvta.to.shared.u64 t, %1; cvt.u32.u64 %0, t; }" : "=r"(a) : "l"(p));
    return a;
}

// pack two fp32 -> one u32 of f16x2 (lo = x, hi = y)
__device__ __forceinline__ uint32_t pack_f16x2(float x, float y) {
    uint32_t h;
    asm("cvt.rn.f16x2.f32 %0, %1, %2;" : "=r"(h) : "f"(y), "f"(x));
    return h;
}

#define CP_ASYNC16(dst, src) \
    asm volatile("cp.async.cg.shared.global [%0], [%1], 16;" :: "r"(dst), "l"(src) : "memory")
#define CP_COMMIT() asm volatile("cp.async.commit_group;" ::: "memory")
#define CP_WAIT0()  asm volatile("cp.async.wait_group 0;" ::: "memory")

#define LDMATRIX_X4(r0, r1, r2, r3, addr)                                    \
    asm volatile("ldmatrix.sync.aligned.m8n8.x4.shared.b16 {%0,%1,%2,%3}, [%4];" \
                 : "=r"(r0), "=r"(r1), "=r"(r2), "=r"(r3) : "r"(addr))

__device__ __forceinline__ void mma_f16(float& d0, float& d1, float& d2, float& d3,
                                        uint32_t a0, uint32_t a1, uint32_t a2, uint32_t a3,
                                        uint32_t b0, uint32_t b1) {
    asm volatile(
        "mma.sync.aligned.m16n8k16.row.col.f32.f16.f16.f32 "
        "{%0,%1,%2,%3}, {%4,%5,%6,%7}, {%8,%9}, {%0,%1,%2,%3};"
        : "+f"(d0), "+f"(d1), "+f"(d2), "+f"(d3)
        : "r"(a0), "r"(a1), "r"(a2), "r"(a3), "r"(b0), "r"(b1));
}

// ============================================================================
// K1: dinv[i] = rsqrt(1 + sum_j adj[i][j])
// ============================================================================
__global__ void __launch_bounds__(256) k1_rowsum(const float* __restrict__ adj) {
    const int row = blockIdx.x;
    const float4* p = reinterpret_cast<const float4*>(adj + (size_t)row * NROWS);
    float s = 0.0f;
    #pragma unroll 4
    for (int i = threadIdx.x; i < NROWS / 4; i += 256) {
        float4 v = p[i];
        s += (v.x + v.y) + (v.z + v.w);
    }
    #pragma unroll
    for (int o = 16; o > 0; o >>= 1) s += __shfl_xor_sync(0xFFFFFFFFu, s, o);
    __shared__ float ws[8];
    if ((threadIdx.x & 31) == 0) ws[threadIdx.x >> 5] = s;
    __syncthreads();
    if (threadIdx.x == 0) {
        float t = 0.0f;
        #pragma unroll
        for (int i = 0; i < 8; i++) t += ws[i];
        g_dinv[row] = rsqrtf(t + 1.0f);
    }
}

// ============================================================================
// K2: zT_h[c][j] = fp16(dinv_j * sum_k x[j][k]*W[c][k]);  z[j][c] fp32
// ============================================================================
__global__ void __launch_bounds__(128) k2_xw(const float* __restrict__ x,
                                             const float* __restrict__ W) {
    extern __shared__ float sh2[];
    float* Ws = sh2;                 // [128][132]
    float* xs = sh2 + 128 * 132;     // [16][128]
    const int c = threadIdx.x;
    const int j0 = blockIdx.x * 16;

    for (int idx = c; idx < 128 * 128; idx += 128)
        Ws[(idx >> 7) * 132 + (idx & 127)] = W[idx];
    for (int idx = c; idx < 16 * 128; idx += 128)
        xs[idx] = x[(size_t)(j0 + (idx >> 7)) * 128 + (idx & 127)];
    __syncthreads();

    float acc[16];
    #pragma unroll
    for (int r = 0; r < 16; r++) acc[r] = 0.0f;
    for (int k = 0; k < 128; k += 4) {
        float4 wv = *reinterpret_cast<const float4*>(&Ws[c * 132 + k]);
        #pragma unroll
        for (int r = 0; r < 16; r++) {
            float4 xv = *reinterpret_cast<const float4*>(&xs[r * 128 + k]);
            acc[r] += xv.x * wv.x + xv.y * wv.y + xv.z * wv.z + xv.w * wv.w;
        }
    }
    float v[16];
    #pragma unroll
    for (int r = 0; r < 16; r++) {
        v[r] = g_dinv[j0 + r] * acc[r];
        g_z[(size_t)(j0 + r) * 128 + c] = v[r];
    }
    // 16 consecutive halves along j for channel c -> 2 x 16B stores
    #pragma unroll
    for (int m = 0; m < 2; m++) {
        uint4 q;
        q.x = pack_f16x2(v[8*m+0], v[8*m+1]);
        q.y = pack_f16x2(v[8*m+2], v[8*m+3]);
        q.z = pack_f16x2(v[8*m+4], v[8*m+5]);
        q.w = pack_f16x2(v[8*m+6], v[8*m+7]);
        *reinterpret_cast<uint4*>(&g_zT_h[(size_t)c * NROWS + j0 + 8 * m]) = q;
    }
}

// ============================================================================
// K3: split-K fp16 mma.sync GEMM: part[ks] = adj[tile,kslice] @ z[kslice,:]
// grid 256 = 64 tiles x 4 ksplits; 256 threads; BM=BN=128, BK=32
// A: LDG fp32 -> cvt -> STS fp16 (register double-buffer)
// B: cp.async fp16 from g_zT_h (L2-resident)
// smem rows: 80B stride (conflict-free ldmatrix), double-buffered
// ============================================================================
static constexpr int BK = 32;
static constexpr int RSTRIDE = 80;                 // bytes per smem row
static constexpr int TILE_B = 128 * RSTRIDE;       // 10240
static constexpr int SMEM_K3 = 4 * TILE_B;         // A0,A1,B0,B1 = 40960

__global__ void __launch_bounds__(256, 2) k3_gemm(const float* __restrict__ adj) {
    extern __shared__ char sm3[];
    const uint32_t base = smem_u32(sm3);
    const int tid = threadIdx.x;
    const int wid = tid >> 5, lane = tid & 31;
    const int gid = lane >> 2, tig = lane & 3;
    const int wm = wid & 3;          // 4 M-warps x 32 rows
    const int wn = wid >> 2;         // 2 N-warps x 64 cols

    const int tile = blockIdx.x & 63;
    const int ks = blockIdx.x >> 6;
    const int m0 = tile * 128;
    const int kbase = ks * 2048;
    const int NK = 2048 / BK;        // 64

    const uint32_t Ab0 = base, Ab1 = base + TILE_B;
    const uint32_t Bb0 = base + 2 * TILE_B, Bb1 = base + 3 * TILE_B;

    // per-thread A load slots: id = tid + 256*i, row=id>>3, qf=id&7 (8 float4/row)
    const int ar[4] = { (tid + 0) >> 3, (tid + 256) >> 3, (tid + 512) >> 3, (tid + 768) >> 3 };
    const int aqf = tid & 7;

    float4 pf[4];
    #define LDA(kt) do {                                                         \
        const int _k0 = kbase + (kt) * BK;                                       \
        _Pragma("unroll")                                                        \
        for (int i = 0; i < 4; i++)                                              \
            pf[i] = *reinterpret_cast<const float4*>(                            \
                adj + (size_t)(m0 + ar[i]) * NROWS + _k0 + aqf * 4);             \
    } while (0)

    #define STA(buf) do {                                                        \
        _Pragma("unroll")                                                        \
        for (int i = 0; i < 4; i++) {                                            \
            uint32_t h0 = pack_f16x2(pf[i].x, pf[i].y);                          \
            uint32_t h1 = pack_f16x2(pf[i].z, pf[i].w);                          \
            asm volatile("st.shared.v2.b32 [%0], {%1,%2};"                       \
                :: "r"((buf) + ar[i] * RSTRIDE + aqf * 8), "r"(h0), "r"(h1)      \
                : "memory");                                                     \
        }                                                                        \
    } while (0)

    #define CPB(kt, buf) do {                                                    \
        const int _k0 = kbase + (kt) * BK;                                       \
        _Pragma("unroll")                                                        \
        for (int i = 0; i < 2; i++) {                                            \
            const int id = tid + 256 * i;                                        \
            const int r = id >> 2, q = id & 3;                                   \
            CP_ASYNC16((buf) + r * RSTRIDE + q * 16,                             \
                       (const void*)(g_zT_h + (size_t)r * NROWS + _k0 + q * 8)); \
        }                                                                        \
    } while (0)

    float acc[2][8][4];
    #pragma unroll
    for (int i = 0; i < 2; i++)
        #pragma unroll
        for (int j = 0; j < 8; j++)
            #pragma unroll
            for (int t = 0; t < 4; t++) acc[i][j][t] = 0.0f;

    LDA(0);
    CPB(0, Bb0); CP_COMMIT();

    for (int kt = 0; kt < NK; kt++) {
        const uint32_t Ab = (kt & 1) ? Ab1 : Ab0;
        const uint32_t Bb = (kt & 1) ? Bb1 : Bb0;
        STA(Ab);
        CP_WAIT0();
        __syncthreads();
        if (kt + 1 < NK) {
            LDA(kt + 1);
            CPB(kt + 1, (kt & 1) ? Bb0 : Bb1);
            CP_COMMIT();
        }
        // -------- mma on (Ab, Bb) --------
        #pragma unroll
        for (int s = 0; s < 2; s++) {                    // k16 steps
            const int ch = 2 * s + (lane >> 4);          // 16B chunk
            uint32_t a[2][4], b[4][4];
            #pragma unroll
            for (int mt = 0; mt < 2; mt++) {
                const int r = wm * 32 + mt * 16 + (lane & 15);
                LDMATRIX_X4(a[mt][0], a[mt][1], a[mt][2], a[mt][3],
                            Ab + r * RSTRIDE + ch * 16);
            }
            #pragma unroll
            for (int p = 0; p < 4; p++) {
                const int r = wn * 64 + p * 16 + (lane & 15);
                LDMATRIX_X4(b[p][0], b[p][1], b[p][2], b[p][3],
                            Bb + r * RSTRIDE + ch * 16);
            }
            #pragma unroll
            for (int mt = 0; mt < 2; mt++)
                #pragma unroll
                for (int nt = 0; nt < 8; nt++) {
                    const int p = nt >> 1, sel = nt & 1;
                    mma_f16(acc[mt][nt][0], acc[mt][nt][1], acc[mt][nt][2], acc[mt][nt][3],
                            a[mt][0], a[mt][1], a[mt][2], a[mt][3],
                            b[p][sel], b[p][2 + sel]);
                }
        }
    }

    // write partials
    float* part = g_part + (size_t)ks * (NROWS * CDIM) + (size_t)m0 * CDIM;
    #pragma unroll
    for (int mt = 0; mt < 2; mt++) {
        const int r0 = wm * 32 + mt * 16 + gid;
        #pragma unroll
        for (int nt = 0; nt < 8; nt++) {
            const int col = wn * 64 + nt * 8 + tig * 2;
            *reinterpret_cast<float2*>(part + (size_t)r0 * 128 + col) =
                make_float2(acc[mt][nt][0], acc[mt][nt][1]);
            *reinterpret_cast<float2*>(part + (size_t)(r0 + 8) * 128 + col) =
                make_float2(acc[mt][nt][2], acc[mt][nt][3]);
        }
    }
    #undef LDA
    #undef STA
    #undef CPB
}

// ============================================================================
// K4: out[i][c] = dinv_i * (sum_s part[s][i][c] + z[i][c]) + b[c]
// ============================================================================
__global__ void __launch_bounds__(256) k4_reduce(const float* __restrict__ bias,
                                                 float* __restrict__ out) {
    const int idx = blockIdx.x * 256 + threadIdx.x;
    const int i = idx >> 5;
    const int c4 = (idx & 31) * 4;
    const size_t off = (size_t)i * 128 + c4;

    float4 s = *reinterpret_cast<const float4*>(g_z + off);
    #pragma unroll
    for (int sp = 0; sp < 4; sp++) {
        float4 p = *reinterpret_cast<const float4*>(g_part + (size_t)sp * (NROWS * CDIM) + off);
        s.x += p.x; s.y += p.y; s.z += p.z; s.w += p.w;
    }
    const float di = g_dinv[i];
    const float4 bb = *reinterpret_cast<const float4*>(bias + c4);
    float4 o;
    o.x = di * s.x + bb.x;
    o.y = di * s.y + bb.y;
    o.z = di * s.z + bb.z;
    o.w = di * s.w + bb.w;
    *reinterpret_cast<float4*>(out + off) = o;
}

// ============================================================================
// launch
// ============================================================================
extern "C" void kernel_launch(void* const* d_in, const int* in_sizes, int n_in,
                              void* d_out, int out_size) {
    (void)in_sizes; (void)n_in; (void)out_size;
    const float* x   = (const float*)d_in[0];
    const float* adj = (const float*)d_in[1];
    const float* W   = (const float*)d_in[2];
    const float* b   = (const float*)d_in[3];
    float* out = (float*)d_out;

    const int smem_k2 = (128 * 132 + 16 * 128) * 4;
    cudaFuncSetAttribute(k2_xw, cudaFuncAttributeMaxDynamicSharedMemorySize, smem_k2);
    cudaFuncSetAttribute(k3_gemm, cudaFuncAttributeMaxDynamicSharedMemorySize, SMEM_K3);

    k1_rowsum<<<NROWS, 256>>>(adj);
    k2_xw<<<NROWS / 16, 128, smem_k2>>>(x, W);
    k3_gemm<<<256, 256, SMEM_K3>>>(adj);
    k4_reduce<<<NROWS * CDIM / 4 / 256, 256>>>(b, out);
}